// round 13
// baseline (speedup 1.0000x reference)
#include <cuda_runtime.h>
#include <cuda_fp16.h>

#define NB 32
#define NN 64

// ---------------- device scratch ----------------
__device__ float g_A[NB * NN * 256];
__device__ float g_C[NB * NN * 256];
__device__ float g_xg[NB * 256];
__device__ unsigned g_cnt[NB];
// 12 pieces of 32KB: p = L*4 + kchunk ; layout [n=256][kchunk=64] f16, XOR-swizzled
__device__ __align__(128) unsigned char g_Wp[12 * 32768];

// smem layout (bytes) for main kernel
#define A_OFF    0            // 4 k-chunks x (128 rows x 128B) = 65536
#define W_OFF    65536        // 2 slots x 64KB (2 pieces each) = 131072
#define BIAS_OFF 196608       // 3 x 256 floats = 3072
#define SMEM_SZ  199680

// ---------------- PTX helpers (family-portable only) ----------------
__device__ __forceinline__ unsigned s2u(const void* p) {
    unsigned a;
    asm("{ .reg .u64 t; cvta.to.shared.u64 t, %1; cvt.u32.u64 %0, t; }" : "=r"(a) : "l"(p));
    return a;
}
__device__ __forceinline__ void ldsm_x4(unsigned addr, unsigned& r0, unsigned& r1,
                                        unsigned& r2, unsigned& r3) {
    asm volatile("ldmatrix.sync.aligned.m8n8.x4.shared.b16 {%0,%1,%2,%3}, [%4];"
                 : "=r"(r0), "=r"(r1), "=r"(r2), "=r"(r3) : "r"(addr));
}
__device__ __forceinline__ void mma_f16(float* c, const unsigned* a, unsigned b0, unsigned b1) {
    asm volatile("mma.sync.aligned.m16n8k16.row.col.f32.f16.f16.f32 "
                 "{%0,%1,%2,%3},{%4,%5,%6,%7},{%8,%9},{%0,%1,%2,%3};"
                 : "+f"(c[0]), "+f"(c[1]), "+f"(c[2]), "+f"(c[3])
                 : "r"(a[0]), "r"(a[1]), "r"(a[2]), "r"(a[3]), "r"(b0), "r"(b1));
}
__device__ __forceinline__ void cpasync16(unsigned s, const void* g) {
    asm volatile("cp.async.cg.shared.global [%0], [%1], 16;" :: "r"(s), "l"(g));
}
#define CP_COMMIT() asm volatile("cp.async.commit_group;" ::: "memory")
#define CP_WAIT0()  asm volatile("cp.async.wait_group 0;" ::: "memory")

__device__ __forceinline__ unsigned cvt_h2(float hi, float lo) {
    unsigned r;
    asm("cvt.rn.f16x2.f32 %0, %1, %2;" : "=r"(r) : "f"(hi), "f"(lo));   // [31:16]=hi,[15:0]=lo
    return r;
}

// ---------------- merged prep (512 threads): A/C precompute (k-split x2) + weight pieces ----------------
__global__ void __launch_bounds__(512) prep_all(
    const float* __restrict__ x_aux, const float* __restrict__ g1w, const float* __restrict__ g1b,
    const float* __restrict__ g2w, const float* __restrict__ g3w, const float* __restrict__ g4w)
{
    int blk = blockIdx.x;
    int tid = threadIdx.x;
    if (blk >= 256) {
        // ---- weight piece p : [n=256][k=64] f16, XOR swizzle; 512 thr -> 16 k2 iters ----
        int p = blk - 256;
        int L = p >> 2, kc = p & 3;
        const float* W = (L == 0) ? g2w : (L == 1) ? g3w : g4w;
        int n = tid & 255, ks = tid >> 8;           // ks = 0/1 : k2 range split
        unsigned char* dst = g_Wp + (size_t)p * 32768;
#pragma unroll 4
        for (int j = 0; j < 16; ++j) {
            int k2 = ks * 16 + j;
            int k = 2 * k2, kg = kc * 64 + k;
            float w0 = W[kg * 256 + n], w1 = W[(kg + 1) * 256 + n];
            unsigned off = (unsigned)n * 128 + ((((unsigned)k >> 3) ^ ((unsigned)n & 7)) << 4)
                         + ((unsigned)k & 7) * 2;
            *(unsigned*)(dst + off) = cvt_h2(w1, w0);
        }
        return;
    }
    // ---- A/C precompute (g1 decomposition), 8 i's per block, k-split x2 ----
    int b = blk >> 3, ig = blk & 7;
    int o = tid & 255, kh = tid >> 8;               // kh = 0/1
    __shared__ float xs[8][128];
    __shared__ float redA[2][8 * 256];
    __shared__ float redC[2][8 * 256];
#pragma unroll
    for (int it = 0; it < 2; ++it) {
        int v = tid + 512 * it, r = v >> 7, k = v & 127;
        xs[r][k] = x_aux[(size_t)(b * 64 + ig * 8 + r) * 128 + k];
    }
    __syncthreads();

    float accA[8], accC[8];
#pragma unroll
    for (int r = 0; r < 8; ++r) { accA[r] = 0.f; accC[r] = 0.f; }

    if (kh == 0) {
        float w64 = g1w[64 * 256 + o], w193 = g1w[193 * 256 + o], bb = g1b[o];
#pragma unroll
        for (int r = 0; r < 8; ++r) {
            float fi = (float)(ig * 8 + r);
            accA[r] = fi * w64;
            accC[r] = fmaf(fi, w193, bb);
        }
    }
    // A rows: kh slice [kh*32, kh*32+32)
#pragma unroll 4
    for (int kk = 0; kk < 32; ++kk) {
        int k = kh * 32 + kk;
        float w = g1w[k * 256 + o];
#pragma unroll
        for (int r = 0; r < 8; ++r) accA[r] = fmaf(xs[r][k], w, accA[r]);
    }
    // C rows: kh slice [kh*64, kh*64+64)
#pragma unroll 4
    for (int kk = 0; kk < 64; ++kk) {
        int k = kh * 64 + kk;
        float w = g1w[(65 + k) * 256 + o];
#pragma unroll
        for (int r = 0; r < 8; ++r) accC[r] = fmaf(xs[r][k], w, accC[r]);
    }
#pragma unroll
    for (int r = 0; r < 8; ++r) {
        redA[kh][r * 256 + o] = accA[r];
        redC[kh][r * 256 + o] = accC[r];
    }
    __syncthreads();
#pragma unroll
    for (int it = 0; it < 4; ++it) {
        int idx = tid + 512 * it;
        int r = idx >> 8, oo = idx & 255;
        int biq = b * 64 + ig * 8 + r;
        g_A[biq * 256 + oo] = redA[0][idx] + redA[1][idx];
        g_C[biq * 256 + oo] = redC[0][idx] + redC[1][idx];
    }
    if (ig == 0 && tid < 256) g_xg[b * 256 + tid] = 0.f;
    if (blk == 0 && tid < NB) g_cnt[tid] = 0u;
}

// ---------------- main: fused g2..g4 on mma.sync f16 + pooling + per-batch f-MLP tail ----------------
__global__ void __launch_bounds__(256, 1) main_kernel(
    const float* __restrict__ g2b, const float* __restrict__ g3b, const float* __restrict__ g4b,
    const float* __restrict__ f1w, const float* __restrict__ f1b,
    const float* __restrict__ f2w, const float* __restrict__ f2b,
    const float* __restrict__ f3w, const float* __restrict__ f3b,
    float* __restrict__ out)
{
    extern __shared__ char smem[];
    unsigned sb = s2u(smem);
    int tid = threadIdx.x, l = tid & 31, wid = tid >> 5;
    int wm = wid & 1, wn = wid >> 1;                    // 2(M) x 4(N) warp grid
    int bi = blockIdx.x;                                // 1024 CTAs
    int b = bi >> 5, i0 = (bi & 31) * 2;

    float* bias_s = (float*)(smem + BIAS_OFF);
    bias_s[tid] = g2b[tid];
    bias_s[256 + tid] = g3b[tid];
    bias_s[512 + tid] = g4b[tid];

    // prologue: async-load pieces 0,1 (64KB) into slot 0
    {
        const unsigned char* src = g_Wp;
        unsigned dst = sb + W_OFF;
#pragma unroll
        for (int i = 0; i < 16; ++i) {
            int off = (tid + 256 * i) * 16;
            cpasync16(dst + off, src + off);
        }
        CP_COMMIT();
    }

    // ---- h1 fill: A chunks <- relu(gA[b,i] + gC[b,j]) as f16, swizzled ----
    {
        int cp = tid & 127, jh = tid >> 7;
        int c0 = 2 * cp;
        float2 av0 = *(const float2*)(g_A + (size_t)(b * 64 + i0) * 256 + c0);
        float2 av1 = *(const float2*)(g_A + (size_t)(b * 64 + i0 + 1) * 256 + c0);
        const float* Cb = g_C + (size_t)(b * 64) * 256;
        unsigned cbase = (unsigned)(c0 >> 6) * 16384;
        unsigned kcol = (unsigned)((c0 & 63) >> 3);
        unsigned kbyt = (unsigned)(c0 & 7) * 2;
#pragma unroll 2
        for (int jj = 0; jj < 32; ++jj) {
            int j = jh * 32 + jj;
            float2 cv = *(const float2*)(Cb + (size_t)j * 256 + c0);
#pragma unroll
            for (int ii = 0; ii < 2; ++ii) {
                int m = ii * 64 + j;
                float ax = ii ? av1.x : av0.x, ay = ii ? av1.y : av0.y;
                float v0 = fmaxf(ax + cv.x, 0.f);
                float v1 = fmaxf(ay + cv.y, 0.f);
                unsigned off = cbase + (unsigned)m * 128
                             + ((kcol ^ ((unsigned)m & 7)) << 4) + kbyt;
                *(unsigned*)(smem + off) = cvt_h2(v1, v0);
            }
        }
    }

    // lane-constant address components
    unsigned arow = (unsigned)(wm * 64 + (l & 15));
    unsigned abase = sb + arow * 128;           // A_OFF = 0
    unsigned asw = (unsigned)(l & 7);
    unsigned ahb = (unsigned)(l >> 4);
    // B ldsm_x4 lane mapping: row=(l&7), k-half=(l>>3)&1, nt-offset=(l>>4)
    unsigned blane = (unsigned)((wn * 64 + (l >> 4) * 8 + (l & 7)) * 128);
    unsigned bsw = (unsigned)(l & 7);
    unsigned bhb = (unsigned)((l >> 3) & 1);

    float acc[4][8][4];
    unsigned esw = (unsigned)(l >> 2);          // row&7 in epilogue
    int cl = l & 3;

    // 6 steps: step t covers pieces 2t, 2t+1 (layer L = t>>1, k-half = t&1)
#pragma unroll 1
    for (int t = 0; t < 6; ++t) {
        CP_WAIT0();
        __syncthreads();          // step-t data visible; all warps finished step t-1
        int slot = t & 1;

        // prefetch step t+1 (64KB) into the other slot BEFORE compute, so the
        // copy overlaps the whole MMA block. That slot was last read in step
        // t-1; the barrier above proves every warp is done with it.
        if (t + 1 < 6) {
            const unsigned char* src = g_Wp + (size_t)(2 * (t + 1)) * 32768;
            unsigned dst = sb + W_OFF + (slot ^ 1) * 65536;
#pragma unroll
            for (int i = 0; i < 16; ++i) {
                int off = (tid + 256 * i) * 16;
                cpasync16(dst + off, src + off);
            }
        }
        CP_COMMIT();

        if ((t & 1) == 0) {
#pragma unroll
            for (int mt = 0; mt < 4; ++mt)
#pragma unroll
                for (int nt = 0; nt < 8; ++nt)
#pragma unroll
                    for (int e = 0; e < 4; ++e) acc[mt][nt][e] = 0.f;
        }

#pragma unroll
        for (int sub = 0; sub < 2; ++sub) {
            int c = (t & 1) * 2 + sub;                 // A k-chunk index
            unsigned acb = abase + (unsigned)c * 16384;
            unsigned bsl = sb + W_OFF + (unsigned)slot * 65536 + (unsigned)sub * 32768 + blane;
#pragma unroll
            for (int ks = 0; ks < 4; ++ks) {
                unsigned a[4][4];
                unsigned kxa = (((unsigned)(ks * 2) + ahb) ^ asw) << 4;
#pragma unroll
                for (int mt = 0; mt < 4; ++mt)
                    ldsm_x4(acb + mt * 2048 + kxa, a[mt][0], a[mt][1], a[mt][2], a[mt][3]);
                unsigned kxb = (((unsigned)(ks * 2) + bhb) ^ bsw) << 4;
#pragma unroll
                for (int np = 0; np < 4; ++np) {
                    unsigned b0, b1, b2, b3;
                    ldsm_x4(bsl + np * 2048 + kxb, b0, b1, b2, b3);
#pragma unroll
                    for (int mt = 0; mt < 4; ++mt) {
                        mma_f16(acc[mt][2 * np], a[mt], b0, b1);
                        mma_f16(acc[mt][2 * np + 1], a[mt], b2, b3);
                    }
                }
            }
        }

        if (t & 1) {
            __syncthreads();      // all MMA reads of A done before rewrite
            int L = t >> 1;
            if (L < 2) {
                // bias+relu, write back as next layer's A (f16, swizzled)
                int r0 = wm * 64 + (l >> 2);
#pragma unroll
                for (int nt = 0; nt < 8; ++nt) {
                    float b0 = bias_s[L * 256 + wn * 64 + nt * 8 + 2 * cl];
                    float b1 = bias_s[L * 256 + wn * 64 + nt * 8 + 2 * cl + 1];
#pragma unroll
                    for (int mt = 0; mt < 4; ++mt) {
                        int ra = r0 + mt * 16, rb = ra + 8;
                        unsigned pa = cvt_h2(fmaxf(acc[mt][nt][1] + b1, 0.f),
                                             fmaxf(acc[mt][nt][0] + b0, 0.f));
                        unsigned pb = cvt_h2(fmaxf(acc[mt][nt][3] + b1, 0.f),
                                             fmaxf(acc[mt][nt][2] + b0, 0.f));
                        unsigned swc = ((unsigned)nt ^ esw) << 4;
                        *(unsigned*)(smem + wn * 16384 + ra * 128 + swc + 4 * cl) = pa;
                        *(unsigned*)(smem + wn * 16384 + rb * 128 + swc + 4 * cl) = pb;
                    }
                }
                __syncthreads();
            } else {
                // g4: bias+relu, row-sum, atomic pool
#pragma unroll
                for (int nt = 0; nt < 8; ++nt) {
                    float b0 = bias_s[512 + wn * 64 + nt * 8 + 2 * cl];
                    float b1 = bias_s[512 + wn * 64 + nt * 8 + 2 * cl + 1];
                    float s0 = 0.f, s1 = 0.f;
#pragma unroll
                    for (int mt = 0; mt < 4; ++mt) {
                        s0 += fmaxf(acc[mt][nt][0] + b0, 0.f) + fmaxf(acc[mt][nt][2] + b0, 0.f);
                        s1 += fmaxf(acc[mt][nt][1] + b1, 0.f) + fmaxf(acc[mt][nt][3] + b1, 0.f);
                    }
                    s0 += __shfl_xor_sync(0xFFFFFFFFu, s0, 4);
                    s0 += __shfl_xor_sync(0xFFFFFFFFu, s0, 8);
                    s0 += __shfl_xor_sync(0xFFFFFFFFu, s0, 16);
                    s1 += __shfl_xor_sync(0xFFFFFFFFu, s1, 4);
                    s1 += __shfl_xor_sync(0xFFFFFFFFu, s1, 8);
                    s1 += __shfl_xor_sync(0xFFFFFFFFu, s1, 16);
                    if (l < 4) {
                        atomicAdd(&g_xg[b * 256 + wn * 64 + nt * 8 + 2 * l], s0);
                        atomicAdd(&g_xg[b * 256 + wn * 64 + nt * 8 + 2 * l + 1], s1);
                    }
                }
            }
        }
    }

    // ---- tail: the last CTA of batch b runs the f-MLP for that batch ----
    __threadfence();                 // release our g_xg atomics
    __syncthreads();
    __shared__ int is_last;
    if (tid == 0) {
        unsigned r = atomicAdd(&g_cnt[b], 1u);
        is_last = (r == 31u);
    }
    __syncthreads();
    if (!is_last) return;
    __threadfence();                 // acquire all other CTAs' g_xg writes

    float* xs  = (float*)smem;               // 256
    float* ys  = (float*)smem + 256;         // 256
    float* red = (float*)smem + 512;         // 8 x 256
    if (tid < 256) xs[tid] = g_xg[b * 256 + tid];
    __syncthreads();

    const float* Ws[3] = {f1w, f2w, f3w};
    const float* Bs[3] = {f1b, f2b, f3b};
#pragma unroll 1
    for (int L = 0; L < 3; ++L) {
        const float* W = Ws[L];
        float a8[8];
#pragma unroll
        for (int oi = 0; oi < 8; ++oi) a8[oi] = 0.f;
#pragma unroll 4
        for (int kk = 0; kk < 32; ++kk) {
            int k = wid * 32 + kk;
            float x = xs[k];
            const float* Wr = W + k * 256 + l;
#pragma unroll
            for (int oi = 0; oi < 8; ++oi) a8[oi] = fmaf(x, Wr[oi * 32], a8[oi]);
        }
#pragma unroll
        for (int oi = 0; oi < 8; ++oi) red[wid * 256 + oi * 32 + l] = a8[oi];
        __syncthreads();
        float s = 0.f;
#pragma unroll
        for (int w = 0; w < 8; ++w) s += red[w * 256 + tid];
        s += Bs[L][tid];
        if (L < 2) {
            ys[tid] = fmaxf(s, 0.f);
        } else {
            out[b * 256 + tid] = s;
        }
        __syncthreads();
        if (L < 2) {
            xs[tid] = ys[tid];
            __syncthreads();
        }
    }
}

// ---------------- launch ----------------
extern "C" void kernel_launch(void* const* d_in, const int* in_sizes, int n_in,
                              void* d_out, int out_size)
{
    const float* x_aux = (const float*)d_in[0];
    const float* g1w   = (const float*)d_in[1];
    const float* g1b   = (const float*)d_in[2];
    const float* g2w   = (const float*)d_in[3];
    const float* g2b   = (const float*)d_in[4];
    const float* g3w   = (const float*)d_in[5];
    const float* g3b   = (const float*)d_in[6];
    const float* g4w   = (const float*)d_in[7];
    const float* g4b   = (const float*)d_in[8];
    const float* f1w   = (const float*)d_in[9];
    const float* f1b   = (const float*)d_in[10];
    const float* f2w   = (const float*)d_in[11];
    const float* f2b   = (const float*)d_in[12];
    const float* f3w   = (const float*)d_in[13];
    const float* f3b   = (const float*)d_in[14];
    float* out = (float*)d_out;

    cudaFuncSetAttribute(main_kernel, cudaFuncAttributeMaxDynamicSharedMemorySize, SMEM_SZ);

    prep_all<<<268, 512>>>(x_aux, g1w, g1b, g2w, g3w, g4w);
    main_kernel<<<1024, 256, SMEM_SZ>>>(g2b, g3b, g4b,
                                        f1w, f1b, f2w, f2b, f3w, f3b, out);
}

// round 14
// speedup vs baseline: 1.2959x; 1.2959x over previous
#include <cuda_runtime.h>
#include <cuda_fp16.h>

#define NB 32
#define NN 64

// ---------------- device scratch ----------------
__device__ float g_A[NB * NN * 256];
__device__ float g_C[NB * NN * 256];
__device__ float g_xg[NB * 256];
// 12 pieces of 32KB: p = L*4 + kchunk ; layout [n=256][kchunk=64] f16, XOR-swizzled
__device__ __align__(128) unsigned char g_Wp[12 * 32768];

// smem layout (bytes) for main kernel
#define A_OFF    0            // 4 k-chunks x (128 rows x 128B) = 65536
#define W_OFF    65536        // 2 slots x 64KB (2 pieces each) = 131072
#define BIAS_OFF 196608       // 3 x 256 floats = 3072
#define SMEM_SZ  199680

// ---------------- PTX helpers (family-portable only) ----------------
__device__ __forceinline__ unsigned s2u(const void* p) {
    unsigned a;
    asm("{ .reg .u64 t; cvta.to.shared.u64 t, %1; cvt.u32.u64 %0, t; }" : "=r"(a) : "l"(p));
    return a;
}
__device__ __forceinline__ void ldsm_x4(unsigned addr, unsigned& r0, unsigned& r1,
                                        unsigned& r2, unsigned& r3) {
    asm volatile("ldmatrix.sync.aligned.m8n8.x4.shared.b16 {%0,%1,%2,%3}, [%4];"
                 : "=r"(r0), "=r"(r1), "=r"(r2), "=r"(r3) : "r"(addr));
}
__device__ __forceinline__ void mma_f16(float* c, const unsigned* a, unsigned b0, unsigned b1) {
    asm volatile("mma.sync.aligned.m16n8k16.row.col.f32.f16.f16.f32 "
                 "{%0,%1,%2,%3},{%4,%5,%6,%7},{%8,%9},{%0,%1,%2,%3};"
                 : "+f"(c[0]), "+f"(c[1]), "+f"(c[2]), "+f"(c[3])
                 : "r"(a[0]), "r"(a[1]), "r"(a[2]), "r"(a[3]), "r"(b0), "r"(b1));
}
__device__ __forceinline__ void cpasync16(unsigned s, const void* g) {
    asm volatile("cp.async.cg.shared.global [%0], [%1], 16;" :: "r"(s), "l"(g));
}
#define CP_COMMIT() asm volatile("cp.async.commit_group;" ::: "memory")
#define CP_WAIT0()  asm volatile("cp.async.wait_group 0;" ::: "memory")

__device__ __forceinline__ unsigned cvt_h2(float hi, float lo) {
    unsigned r;
    asm("cvt.rn.f16x2.f32 %0, %1, %2;" : "=r"(r) : "f"(hi), "f"(lo));   // [31:16]=hi,[15:0]=lo
    return r;
}

// ---------------- merged prep (512 threads): A/C precompute (k-split x2) + weight pieces ----------------
__global__ void __launch_bounds__(512) prep_all(
    const float* __restrict__ x_aux, const float* __restrict__ g1w, const float* __restrict__ g1b,
    const float* __restrict__ g2w, const float* __restrict__ g3w, const float* __restrict__ g4w)
{
    int blk = blockIdx.x;
    int tid = threadIdx.x;
    if (blk >= 256) {
        // ---- weight piece p : [n=256][k=64] f16, XOR swizzle; 512 thr -> 16 k2 iters ----
        int p = blk - 256;
        int L = p >> 2, kc = p & 3;
        const float* W = (L == 0) ? g2w : (L == 1) ? g3w : g4w;
        int n = tid & 255, ks = tid >> 8;           // ks = 0/1 : k2 range split
        unsigned char* dst = g_Wp + (size_t)p * 32768;
#pragma unroll 4
        for (int j = 0; j < 16; ++j) {
            int k2 = ks * 16 + j;
            int k = 2 * k2, kg = kc * 64 + k;
            float w0 = W[kg * 256 + n], w1 = W[(kg + 1) * 256 + n];
            unsigned off = (unsigned)n * 128 + ((((unsigned)k >> 3) ^ ((unsigned)n & 7)) << 4)
                         + ((unsigned)k & 7) * 2;
            *(unsigned*)(dst + off) = cvt_h2(w1, w0);
        }
        return;
    }
    // ---- A/C precompute (g1 decomposition), 8 i's per block, k-split x2 ----
    int b = blk >> 3, ig = blk & 7;
    int o = tid & 255, kh = tid >> 8;               // kh = 0/1
    __shared__ float xs[8][128];
    __shared__ float redA[2][8 * 256];
    __shared__ float redC[2][8 * 256];
#pragma unroll
    for (int it = 0; it < 2; ++it) {
        int v = tid + 512 * it, r = v >> 7, k = v & 127;
        xs[r][k] = x_aux[(size_t)(b * 64 + ig * 8 + r) * 128 + k];
    }
    __syncthreads();

    float accA[8], accC[8];
#pragma unroll
    for (int r = 0; r < 8; ++r) { accA[r] = 0.f; accC[r] = 0.f; }

    if (kh == 0) {
        float w64 = g1w[64 * 256 + o], w193 = g1w[193 * 256 + o], bb = g1b[o];
#pragma unroll
        for (int r = 0; r < 8; ++r) {
            float fi = (float)(ig * 8 + r);
            accA[r] = fi * w64;
            accC[r] = fmaf(fi, w193, bb);
        }
    }
#pragma unroll 4
    for (int kk = 0; kk < 32; ++kk) {
        int k = kh * 32 + kk;
        float w = g1w[k * 256 + o];
#pragma unroll
        for (int r = 0; r < 8; ++r) accA[r] = fmaf(xs[r][k], w, accA[r]);
    }
#pragma unroll 4
    for (int kk = 0; kk < 64; ++kk) {
        int k = kh * 64 + kk;
        float w = g1w[(65 + k) * 256 + o];
#pragma unroll
        for (int r = 0; r < 8; ++r) accC[r] = fmaf(xs[r][k], w, accC[r]);
    }
#pragma unroll
    for (int r = 0; r < 8; ++r) {
        redA[kh][r * 256 + o] = accA[r];
        redC[kh][r * 256 + o] = accC[r];
    }
    __syncthreads();
#pragma unroll
    for (int it = 0; it < 4; ++it) {
        int idx = tid + 512 * it;
        int r = idx >> 8, oo = idx & 255;
        int biq = b * 64 + ig * 8 + r;
        g_A[biq * 256 + oo] = redA[0][idx] + redA[1][idx];
        g_C[biq * 256 + oo] = redC[0][idx] + redC[1][idx];
    }
    if (ig == 0 && tid < 256) g_xg[b * 256 + tid] = 0.f;
}

// ---------------- main: fused g2..g4 on mma.sync f16 + pooling (512 threads, 2x8 warps) ----------------
__global__ void __launch_bounds__(512, 1) main_kernel(
    const float* __restrict__ g2b, const float* __restrict__ g3b, const float* __restrict__ g4b)
{
    extern __shared__ char smem[];
    unsigned sb = s2u(smem);
    int tid = threadIdx.x, l = tid & 31, wid = tid >> 5;
    int wm = wid & 1, wn = wid >> 1;                    // 2(M) x 8(N) warp grid
    int bi = blockIdx.x;                                // 1024 CTAs
    int b = bi >> 5, i0 = (bi & 31) * 2;

    float* bias_s = (float*)(smem + BIAS_OFF);
    if (tid < 256) {
        bias_s[tid] = g2b[tid];
        bias_s[256 + tid] = g3b[tid];
        bias_s[512 + tid] = g4b[tid];
    }

    // prologue: async-load pieces 0,1 (64KB) into slot 0
    {
        const unsigned char* src = g_Wp;
        unsigned dst = sb + W_OFF;
#pragma unroll
        for (int i = 0; i < 8; ++i) {
            int off = (tid + 512 * i) * 16;
            cpasync16(dst + off, src + off);
        }
        CP_COMMIT();
    }

    // ---- h1 fill: A chunks <- relu(gA[b,i] + gC[b,j]) as f16, swizzled ----
    {
        int cp = tid & 127, jh = tid >> 7;      // jh = 0..3, 16 j's each
        int c0 = 2 * cp;
        float2 av0 = *(const float2*)(g_A + (size_t)(b * 64 + i0) * 256 + c0);
        float2 av1 = *(const float2*)(g_A + (size_t)(b * 64 + i0 + 1) * 256 + c0);
        const float* Cb = g_C + (size_t)(b * 64) * 256;
        unsigned cbase = (unsigned)(c0 >> 6) * 16384;
        unsigned kcol = (unsigned)((c0 & 63) >> 3);
        unsigned kbyt = (unsigned)(c0 & 7) * 2;
#pragma unroll 2
        for (int jj = 0; jj < 16; ++jj) {
            int j = jh * 16 + jj;
            float2 cv = *(const float2*)(Cb + (size_t)j * 256 + c0);
#pragma unroll
            for (int ii = 0; ii < 2; ++ii) {
                int m = ii * 64 + j;
                float ax = ii ? av1.x : av0.x, ay = ii ? av1.y : av0.y;
                float v0 = fmaxf(ax + cv.x, 0.f);
                float v1 = fmaxf(ay + cv.y, 0.f);
                unsigned off = cbase + (unsigned)m * 128
                             + ((kcol ^ ((unsigned)m & 7)) << 4) + kbyt;
                *(unsigned*)(smem + off) = cvt_h2(v1, v0);
            }
        }
    }

    // lane-constant address components
    unsigned arow = (unsigned)(wm * 64 + (l & 15));
    unsigned abase = sb + arow * 128;           // A_OFF = 0
    unsigned asw = (unsigned)(l & 7);
    unsigned ahb = (unsigned)(l >> 4);
    // B ldsm_x4 lane mapping: rows wn*32 + np2*16 + (l>>4)*8 + (l&7); k-half (l>>3)&1
    unsigned blane = (unsigned)((wn * 32 + (l >> 4) * 8 + (l & 7)) * 128);
    unsigned bsw = (unsigned)(l & 7);
    unsigned bhb = (unsigned)((l >> 3) & 1);

    float acc[4][4][4];                         // mt x nt x quad
    unsigned esw = (unsigned)(l >> 2);          // row&7 in epilogue
    int cl = l & 3;

    // 6 steps: step t covers pieces 2t, 2t+1 (layer L = t>>1, k-half = t&1)
#pragma unroll 1
    for (int t = 0; t < 6; ++t) {
        CP_WAIT0();
        __syncthreads();          // step-t data visible; all warps finished step t-1
        int slot = t & 1;

        // prefetch step t+1 into the other slot BEFORE compute (overlaps MMA)
        if (t + 1 < 6) {
            const unsigned char* src = g_Wp + (size_t)(2 * (t + 1)) * 32768;
            unsigned dst = sb + W_OFF + (slot ^ 1) * 65536;
#pragma unroll
            for (int i = 0; i < 8; ++i) {
                int off = (tid + 512 * i) * 16;
                cpasync16(dst + off, src + off);
            }
        }
        CP_COMMIT();

        if ((t & 1) == 0) {
#pragma unroll
            for (int mt = 0; mt < 4; ++mt)
#pragma unroll
                for (int nt = 0; nt < 4; ++nt)
#pragma unroll
                    for (int e = 0; e < 4; ++e) acc[mt][nt][e] = 0.f;
        }

#pragma unroll
        for (int sub = 0; sub < 2; ++sub) {
            int c = (t & 1) * 2 + sub;                 // A k-chunk index
            unsigned acb = abase + (unsigned)c * 16384;
            unsigned bsl = sb + W_OFF + (unsigned)slot * 65536 + (unsigned)sub * 32768 + blane;
#pragma unroll
            for (int ks = 0; ks < 4; ++ks) {
                unsigned a[4][4];
                unsigned kxa = (((unsigned)(ks * 2) + ahb) ^ asw) << 4;
#pragma unroll
                for (int mt = 0; mt < 4; ++mt)
                    ldsm_x4(acb + mt * 2048 + kxa, a[mt][0], a[mt][1], a[mt][2], a[mt][3]);
                unsigned kxb = (((unsigned)(ks * 2) + bhb) ^ bsw) << 4;
#pragma unroll
                for (int np2 = 0; np2 < 2; ++np2) {
                    unsigned b0, b1, b2, b3;
                    ldsm_x4(bsl + np2 * 2048 + kxb, b0, b1, b2, b3);
#pragma unroll
                    for (int mt = 0; mt < 4; ++mt) {
                        mma_f16(acc[mt][2 * np2], a[mt], b0, b1);
                        mma_f16(acc[mt][2 * np2 + 1], a[mt], b2, b3);
                    }
                }
            }
        }

        if (t & 1) {
            __syncthreads();      // all MMA reads of A done before rewrite
            int L = t >> 1;
            if (L < 2) {
                // bias+relu, write back as next layer's A (f16, swizzled)
                // warp wn owns out-cols [wn*32, wn*32+32): chunk = wn>>1, base k = (wn&1)*32
                int r0 = wm * 64 + (l >> 2);
                unsigned chunk_base = (unsigned)(wn >> 1) * 16384;
#pragma unroll
                for (int nt = 0; nt < 4; ++nt) {
                    int bcol = wn * 32 + nt * 8;
                    float b0 = bias_s[L * 256 + bcol + 2 * cl];
                    float b1 = bias_s[L * 256 + bcol + 2 * cl + 1];
                    unsigned kcol8 = (unsigned)((wn & 1) * 4 + nt);
                    unsigned swc = (kcol8 ^ esw) << 4;
#pragma unroll
                    for (int mt = 0; mt < 4; ++mt) {
                        int ra = r0 + mt * 16, rb = ra + 8;
                        unsigned pa = cvt_h2(fmaxf(acc[mt][nt][1] + b1, 0.f),
                                             fmaxf(acc[mt][nt][0] + b0, 0.f));
                        unsigned pb = cvt_h2(fmaxf(acc[mt][nt][3] + b1, 0.f),
                                             fmaxf(acc[mt][nt][2] + b0, 0.f));
                        *(unsigned*)(smem + chunk_base + ra * 128 + swc + 4 * cl) = pa;
                        *(unsigned*)(smem + chunk_base + rb * 128 + swc + 4 * cl) = pb;
                    }
                }
                __syncthreads();
            } else {
                // g4: bias+relu, row-sum over this warp's 64 rows, atomic pool
#pragma unroll
                for (int nt = 0; nt < 4; ++nt) {
                    int bcol = wn * 32 + nt * 8;
                    float b0 = bias_s[512 + bcol + 2 * cl];
                    float b1 = bias_s[512 + bcol + 2 * cl + 1];
                    float s0 = 0.f, s1 = 0.f;
#pragma unroll
                    for (int mt = 0; mt < 4; ++mt) {
                        s0 += fmaxf(acc[mt][nt][0] + b0, 0.f) + fmaxf(acc[mt][nt][2] + b0, 0.f);
                        s1 += fmaxf(acc[mt][nt][1] + b1, 0.f) + fmaxf(acc[mt][nt][3] + b1, 0.f);
                    }
                    s0 += __shfl_xor_sync(0xFFFFFFFFu, s0, 4);
                    s0 += __shfl_xor_sync(0xFFFFFFFFu, s0, 8);
                    s0 += __shfl_xor_sync(0xFFFFFFFFu, s0, 16);
                    s1 += __shfl_xor_sync(0xFFFFFFFFu, s1, 4);
                    s1 += __shfl_xor_sync(0xFFFFFFFFu, s1, 8);
                    s1 += __shfl_xor_sync(0xFFFFFFFFu, s1, 16);
                    if (l < 4) {
                        atomicAdd(&g_xg[b * 256 + bcol + 2 * l], s0);
                        atomicAdd(&g_xg[b * 256 + bcol + 2 * l + 1], s1);
                    }
                }
            }
        }
    }
}

// ---------------- fused f-MLP: one launch, 32 CTAs x 1024 threads, 4-way k-split ----------------
__global__ void __launch_bounds__(1024) f_fused(
    const float* __restrict__ f1w, const float* __restrict__ f1b,
    const float* __restrict__ f2w, const float* __restrict__ f2b,
    const float* __restrict__ f3w, const float* __restrict__ f3b,
    float* __restrict__ out)
{
    int b = blockIdx.x;
    int tid = threadIdx.x;
    int o = tid & 255, kp = tid >> 8;          // 4 k-parts of 64
    __shared__ float xs[256];
    __shared__ float ys[256];
    __shared__ float red[4][256];

    if (tid < 256) xs[tid] = g_xg[b * 256 + tid];
    __syncthreads();

    // layer 1
    {
        float acc = 0.f;
#pragma unroll 8
        for (int kk = 0; kk < 64; ++kk) {
            int k = kp * 64 + kk;
            acc = fmaf(xs[k], f1w[k * 256 + o], acc);
        }
        red[kp][o] = acc;
        __syncthreads();
        if (tid < 256) {
            float s = red[0][tid] + red[1][tid] + red[2][tid] + red[3][tid] + f1b[tid];
            ys[tid] = fmaxf(s, 0.f);
        }
        __syncthreads();
    }
    // layer 2
    {
        float acc = 0.f;
#pragma unroll 8
        for (int kk = 0; kk < 64; ++kk) {
            int k = kp * 64 + kk;
            acc = fmaf(ys[k], f2w[k * 256 + o], acc);
        }
        red[kp][o] = acc;
        __syncthreads();
        if (tid < 256) {
            float s = red[0][tid] + red[1][tid] + red[2][tid] + red[3][tid] + f2b[tid];
            xs[tid] = fmaxf(s, 0.f);
        }
        __syncthreads();
    }
    // layer 3
    {
        float acc = 0.f;
#pragma unroll 8
        for (int kk = 0; kk < 64; ++kk) {
            int k = kp * 64 + kk;
            acc = fmaf(xs[k], f3w[k * 256 + o], acc);
        }
        red[kp][o] = acc;
        __syncthreads();
        if (tid < 256)
            out[b * 256 + tid] = red[0][tid] + red[1][tid] + red[2][tid] + red[3][tid] + f3b[tid];
    }
}

// ---------------- launch ----------------
extern "C" void kernel_launch(void* const* d_in, const int* in_sizes, int n_in,
                              void* d_out, int out_size)
{
    const float* x_aux = (const float*)d_in[0];
    const float* g1w   = (const float*)d_in[1];
    const float* g1b   = (const float*)d_in[2];
    const float* g2w   = (const float*)d_in[3];
    const float* g2b   = (const float*)d_in[4];
    const float* g3w   = (const float*)d_in[5];
    const float* g3b   = (const float*)d_in[6];
    const float* g4w   = (const float*)d_in[7];
    const float* g4b   = (const float*)d_in[8];
    const float* f1w   = (const float*)d_in[9];
    const float* f1b   = (const float*)d_in[10];
    const float* f2w   = (const float*)d_in[11];
    const float* f2b   = (const float*)d_in[12];
    const float* f3w   = (const float*)d_in[13];
    const float* f3b   = (const float*)d_in[14];
    float* out = (float*)d_out;

    cudaFuncSetAttribute(main_kernel, cudaFuncAttributeMaxDynamicSharedMemorySize, SMEM_SZ);

    prep_all<<<268, 512>>>(x_aux, g1w, g1b, g2w, g3w, g4w);
    main_kernel<<<1024, 512, SMEM_SZ>>>(g2b, g3b, g4b);
    f_fused<<<NB, 1024>>>(f1w, f1b, f2w, f2b, f3w, f3b, out);
}